// round 1
// baseline (speedup 1.0000x reference)
#include <cuda_runtime.h>
#include <cuda_bf16.h>
#include <cstdint>

// GIB_Layer: M=50000 queries, K=32 support, 4 kinds x G=8 gaussian basis fns,
// masked mean over K, then (4G x OBS) mixing matmul. REACH=1, EPS=1e-8.
//
// Strategy: warp per query. Lane k owns neighbor k. Mask density ~8%, so we
// ballot-compact and only evaluate exp for active neighbors; for each active
// neighbor, the 32 weight evaluations (kind,g) are spread across the 32 lanes
// in a unified coefficient form: w = 2^(a*x2 + b*y2 + c*z2 + d*(rxy*z) + k0).

#define GIB_K     32
#define GIB_G     8
#define GIB_OBS   16
#define GIB_F     32          // 4*G features
#define GIB_EPS   1e-8f
#define WPB       8           // warps per block
#define LOG2E     1.4426950408889634f

__device__ __forceinline__ float fast_exp2(float x) {
    float y;
    asm("ex2.approx.ftz.f32 %0, %1;" : "=f"(y) : "f"(x));
    return y;
}

__global__ __launch_bounds__(WPB * 32, 8)
void gib_layer_kernel(const float* __restrict__ points,
                      const float* __restrict__ q_coords,
                      const int*   __restrict__ support_idxs,
                      const float* __restrict__ cy_radius,
                      const float* __restrict__ disk_radius,
                      const float* __restrict__ disk_width,
                      const float* __restrict__ cone_radius,
                      const float* __restrict__ cone_inc,
                      const float* __restrict__ ellip_radii,
                      const float* __restrict__ lambdas,
                      float* __restrict__ out,
                      int M)
{
    __shared__ float s_lam[GIB_F * GIB_OBS];        // 512 floats
    __shared__ float s_feat[WPB][GIB_F + 1];        // +1 pad (paranoia)

    // Stage lambdas into shared once per block.
    for (int i = threadIdx.x; i < GIB_F * GIB_OBS; i += blockDim.x)
        s_lam[i] = lambdas[i];

    const int lane = threadIdx.x & 31;
    const int wid  = threadIdx.x >> 5;
    const int m    = blockIdx.x * WPB + wid;

    // ---- per-lane weight coefficients: lane -> (kind = lane>>3, g = lane&7)
    // unified exponent (base 2): a*x2 + b*y2 + c*z2 + d*rz + k0,  rz = sqrt(xy2+EPS)*z
    const int kind = lane >> 3;
    const int g    = lane & 7;
    float a, b, c, d, k0;
    {
        const float NHL = -0.5f * LOG2E;  // fold -1/2 and ln->log2 conversion
        if (kind == 0) {                  // cylinder: exp(-xy2 / (2 r^2))
            float r = cy_radius[g];
            float P = NHL / (r * r + GIB_EPS);
            a = P; b = P; c = 0.f; d = 0.f; k0 = 0.f;
        } else if (kind == 1) {           // cone: exp(-(rxy - z*inc)^2 / (2 r^2))
            float r   = cone_radius[g];
            float inc = cone_inc[g];
            float Q = NHL / (r * r + GIB_EPS);
            // (rxy - z*inc)^2 = (xy2+EPS) - 2*rz*inc + z2*inc^2
            a = Q; b = Q; c = Q * inc * inc; d = -2.f * Q * inc; k0 = Q * GIB_EPS;
        } else if (kind == 2) {           // disk: exp(-0.5*(xy2/dr^2 + z2/dw^2))
            float dr = disk_radius[g], dw = disk_width[g];
            float Dr = NHL / (dr * dr + GIB_EPS);
            float Dw = NHL / (dw * dw + GIB_EPS);
            a = Dr; b = Dr; c = Dw; d = 0.f; k0 = 0.f;
        } else {                          // ellipsoid: per-axis radii
            float ra = ellip_radii[g * 3 + 0];
            float rb = ellip_radii[g * 3 + 1];
            float rc = ellip_radii[g * 3 + 2];
            a = NHL / (ra * ra + GIB_EPS);
            b = NHL / (rb * rb + GIB_EPS);
            c = NHL / (rc * rc + GIB_EPS);
            d = 0.f; k0 = 0.f;
        }
    }

    __syncthreads();                      // s_lam ready
    if (m >= M) return;                   // whole warp exits together

    // ---- gather: lane k handles neighbor k
    const float qx = q_coords[3 * m + 0];
    const float qy = q_coords[3 * m + 1];
    const float qz = q_coords[3 * m + 2];

    const int pi = support_idxs[m * GIB_K + lane];
    const float x = points[3 * pi + 0] - qx;
    const float y = points[3 * pi + 1] - qy;
    const float z = points[3 * pi + 2] - qz;

    const float x2 = x * x, y2 = y * y, z2 = z * z;
    const float d2 = x2 + y2 + z2;
    const float rz = sqrtf(x2 + y2 + GIB_EPS) * z;
    const bool  active = (d2 <= 1.0f);    // REACH^2 = 1

    unsigned bal = __ballot_sync(0xffffffffu, active);
    float acc = 0.f;
    while (bal) {
        const int j = __ffs(bal) - 1;
        bal &= bal - 1;
        const float bx2 = __shfl_sync(0xffffffffu, x2, j);
        const float by2 = __shfl_sync(0xffffffffu, y2, j);
        const float bz2 = __shfl_sync(0xffffffffu, z2, j);
        const float brz = __shfl_sync(0xffffffffu, rz, j);
        const float arg = fmaf(a, bx2, fmaf(b, by2, fmaf(c, bz2, fmaf(d, brz, k0))));
        acc += fast_exp2(arg);
    }
    acc *= (1.0f / (float)GIB_K);         // masked mean: sum(active w)/K

    s_feat[wid][lane] = acc;
    __syncwarp();

    // ---- epilogue: out[m, o] = sum_f feat[f] * lambdas[f, o]
    if (lane < GIB_OBS) {
        float o = 0.f;
        #pragma unroll
        for (int f = 0; f < GIB_F; f++)
            o = fmaf(s_feat[wid][f], s_lam[f * GIB_OBS + lane], o);
        out[m * GIB_OBS + lane] = o;
    }
}

extern "C" void kernel_launch(void* const* d_in, const int* in_sizes, int n_in,
                              void* d_out, int out_size)
{
    const float* points       = (const float*)d_in[0];
    const float* q_coords     = (const float*)d_in[1];
    const int*   support_idxs = (const int*)  d_in[2];
    const float* cy_radius    = (const float*)d_in[3];
    const float* disk_radius  = (const float*)d_in[4];
    const float* disk_width   = (const float*)d_in[5];
    const float* cone_radius  = (const float*)d_in[6];
    const float* cone_inc     = (const float*)d_in[7];
    const float* ellip_radii  = (const float*)d_in[8];
    const float* lambdas      = (const float*)d_in[9];
    float* out = (float*)d_out;

    const int M = in_sizes[1] / 3;        // q_coords is (M, 3)
    const int blocks = (M + WPB - 1) / WPB;

    gib_layer_kernel<<<blocks, WPB * 32>>>(points, q_coords, support_idxs,
                                           cy_radius, disk_radius, disk_width,
                                           cone_radius, cone_inc, ellip_radii,
                                           lambdas, out, M);
}